// round 6
// baseline (speedup 1.0000x reference)
#include <cuda_runtime.h>
#include <cuda_bf16.h>
#include <cstdint>

#define NB   16
#define SEQ  1024
#define HID  768
#define SCALE_QK 0.03608439182435161f

#define BM 128
#define BN 256
#define BK 32
#define NTHREADS 256
#define ASZ 10240             /* A hi (or lo) bytes: 128 rows * 80 */
#define BSZ 20480             /* B hi (or lo) bytes: 256 rows * 80 */
#define STAGE_BYTES 61440     /* Ah,Al,Bh,Bl */
#define NSTAGES 3
#define SMEM_GEMM (NSTAGES*STAGE_BYTES)
#define BNN_LD 528            /* nn-mode B row stride: 256*2+16 */

typedef __nv_bfloat16 bf16;

/* ------------------ scratch (device globals) ------------------ */
#define NXE 12582912   /* 16*1024*768 */
#define NWE 589824     /* 768*768 */
#define NSE 16777216   /* 16*1024*1024 */
__device__ bf16 g_xh[NXE],  g_xl[NXE];
__device__ bf16 g_qh[NXE],  g_ql[NXE];
__device__ bf16 g_kh[NXE],  g_kl[NXE];
__device__ bf16 g_vh[NXE],  g_vl[NXE];
__device__ bf16 g_oh[NXE],  g_ol[NXE];
__device__ bf16 g_h1h[NXE], g_h1l[NXE];
__device__ bf16 g_wqh[NWE], g_wql[NWE], g_wkh[NWE], g_wkl[NWE], g_wvh[NWE], g_wvl[NWE];
__device__ bf16 g_w1h[NWE], g_w1l[NWE], g_w2h[NWE], g_w2l[NWE];
__device__ float g_sc[NSE];
__device__ bf16 g_wh[NSE],  g_wl[NSE];
__device__ float g_of[NXE];

/* ------------------ helpers ------------------ */
static __device__ __forceinline__ uint32_t smem_u32(const void* p) {
    uint32_t a;
    asm("{ .reg .u64 t; cvta.to.shared.u64 t, %1; cvt.u32.u64 %0, t; }" : "=r"(a) : "l"(p));
    return a;
}
static __device__ __forceinline__ uint32_t pack_bf2(float v0, float v1) {
    uint32_t d;  /* memory order v0,v1 */
    asm("cvt.rn.bf16x2.f32 %0, %1, %2;" : "=r"(d) : "f"(v1), "f"(v0));
    return d;
}
static __device__ __forceinline__ void split2(float v0, float v1, uint32_t& h, uint32_t& l) {
    h = pack_bf2(v0, v1);
    float h0 = __uint_as_float(h << 16);
    float h1 = __uint_as_float(h & 0xFFFF0000u);
    l = pack_bf2(v0 - h0, v1 - h1);
}

#define CP16(dst, src) \
    asm volatile("cp.async.cg.shared.global [%0], [%1], 16;" :: "r"(dst), "l"(src))
#define CPCOMMIT() asm volatile("cp.async.commit_group;" ::: "memory")
#define CPWAIT1()  asm volatile("cp.async.wait_group 1;" ::: "memory")

#define LDSM4(r, a) \
    asm volatile("ldmatrix.sync.aligned.m8n8.x4.shared.b16 {%0,%1,%2,%3}, [%4];" \
        : "=r"((r)[0]),"=r"((r)[1]),"=r"((r)[2]),"=r"((r)[3]) : "r"(a))
#define LDSM4T(r, a) \
    asm volatile("ldmatrix.sync.aligned.m8n8.x4.trans.shared.b16 {%0,%1,%2,%3}, [%4];" \
        : "=r"((r)[0]),"=r"((r)[1]),"=r"((r)[2]),"=r"((r)[3]) : "r"(a))
#define MMA(c, a, b0, b1) \
    asm volatile("mma.sync.aligned.m16n8k16.row.col.f32.bf16.bf16.f32 " \
        "{%0,%1,%2,%3}, {%4,%5,%6,%7}, {%8,%9}, {%0,%1,%2,%3};" \
        : "+f"((c)[0]), "+f"((c)[1]), "+f"((c)[2]), "+f"((c)[3]) \
        : "r"((a)[0]),"r"((a)[1]),"r"((a)[2]),"r"((a)[3]), "r"(b0), "r"(b1))

/* fp32 -> bf16 hi/lo conversion (pre-pass) */
__global__ __launch_bounds__(256) void cvt_kernel(
    const float* __restrict__ in, uint32_t* __restrict__ oh,
    uint32_t* __restrict__ ol, int n2)
{
    int i = blockIdx.x * 256 + threadIdx.x;
    if (i < n2) {
        float2 v = reinterpret_cast<const float2*>(in)[i];
        uint32_t h, l; split2(v.x, v.y, h, l);
        oh[i] = h; ol[i] = l;
    }
}

/* ---------------------------------------------------------------------------
 * bf16 split GEMM, mma.sync m16n8k16.
 * CTA tile 128x256xBK32, 8 warps in 2(m) x 4(n), warp tile 64x64.
 * 3-stage cp.async pipeline, ONE __syncthreads per stage.
 * nn=0: C = A[M,K] * B[N,K]^T ; nn=1: C = A[M,K] * B[K,N] (ldbn row stride).
 * ------------------------------------------------------------------------ */
__global__ __launch_bounds__(NTHREADS, 1) void gemm_bf(
    const bf16* __restrict__ Ah, const bf16* __restrict__ Al,
    const bf16* __restrict__ Bh, const bf16* __restrict__ Bl,
    int K, int nn, int ldbn,
    size_t sA, size_t sB, size_t sC,
    float* __restrict__ Cf, bf16* __restrict__ Ch, bf16* __restrict__ Cl,
    int ldc, const float* __restrict__ bias, const float* __restrict__ res,
    const int* __restrict__ mask, int relu)
{
    extern __shared__ char smraw[];
    const uint32_t sb = smem_u32(smraw);
    const int tid = threadIdx.x, lane = tid & 31, wid = tid >> 5;
    const int wm = wid & 1, wn = wid >> 1;            /* 2 x 4 warp grid */
    const int z = blockIdx.z, bm = blockIdx.y * BM, bn = blockIdx.x * BN;

    const bf16* Ahg = Ah + z * sA + (size_t)bm * K;
    const bf16* Alg = Al + z * sA + (size_t)bm * K;
    const bf16 *Bhg, *Blg;
    if (nn) { Bhg = Bh + z * sB + bn;              Blg = Bl + z * sB + bn; }
    else    { Bhg = Bh + z * sB + (size_t)bn * K;  Blg = Bl + z * sB + (size_t)bn * K; }

    float acc[4][8][4];
    #pragma unroll
    for (int i = 0; i < 4; i++)
        #pragma unroll
        for (int j = 0; j < 8; j++)
            #pragma unroll
            for (int t = 0; t < 4; t++) acc[i][j][t] = 0.f;

    auto issue = [&](int s) {
        const uint32_t stb = sb + (uint32_t)(s % NSTAGES) * STAGE_BYTES;
        const int k0 = s * BK;
        /* A: 128 rows x 32 cols (hi+lo) */
        #pragma unroll
        for (int i = 0; i < 2; i++) {
            const int idx = tid + (i << 8);
            const int row = idx >> 2, c8 = (idx & 3) << 3;
            const uint32_t da = stb + row * 80 + (c8 << 1);
            CP16(da,       Ahg + (size_t)row * K + k0 + c8);
            CP16(da + ASZ, Alg + (size_t)row * K + k0 + c8);
        }
        if (!nn) {
            /* B: 256 rows x 32 cols, K-major */
            #pragma unroll
            for (int i = 0; i < 4; i++) {
                const int idx = tid + (i << 8);
                const int row = idx >> 2, c8 = (idx & 3) << 3;
                const uint32_t db = stb + 2 * ASZ + row * 80 + (c8 << 1);
                CP16(db,       Bhg + (size_t)row * K + k0 + c8);
                CP16(db + BSZ, Blg + (size_t)row * K + k0 + c8);
            }
        } else {
            /* B: 32 rows x 256 cols, N-major */
            #pragma unroll
            for (int i = 0; i < 4; i++) {
                const int idx = tid + (i << 8);
                const int row = idx >> 5, c8 = (idx & 31) << 3;
                const uint32_t db = stb + 2 * ASZ + row * BNN_LD + (c8 << 1);
                CP16(db,       Bhg + (size_t)(k0 + row) * ldbn + c8);
                CP16(db + BSZ, Blg + (size_t)(k0 + row) * ldbn + c8);
            }
        }
    };

    auto compute = [&](int s) {
        const uint32_t stb = sb + (uint32_t)(s % NSTAGES) * STAGE_BYTES;
        #pragma unroll
        for (int ks = 0; ks < 2; ks++) {
            uint32_t ah[4][4], al[4][4];
            #pragma unroll
            for (int i = 0; i < 4; i++) {
                const int arow = wm * 64 + i * 16 + (lane & 15);
                const uint32_t ad = stb + arow * 80 + ((ks * 16 + ((lane >> 4) << 3)) << 1);
                LDSM4(ah[i], ad);
                LDSM4(al[i], ad + ASZ);
            }
            #pragma unroll
            for (int p = 0; p < 4; p++) {
                uint32_t bh[4], bl[4];
                if (!nn) {
                    const int brow = wn * 64 + p * 16 + (lane & 7) + ((lane >> 4) << 3);
                    const uint32_t bd = stb + 2 * ASZ + brow * 80 +
                                        ((ks * 16 + (((lane >> 3) & 1) << 3)) << 1);
                    LDSM4(bh, bd);
                    LDSM4(bl, bd + BSZ);
                } else {
                    const int krow = ks * 16 + (lane & 7) + (((lane >> 3) & 1) << 3);
                    const int ncol = wn * 64 + p * 16 + ((lane >> 4) << 3);
                    const uint32_t bd = stb + 2 * ASZ + krow * BNN_LD + (ncol << 1);
                    LDSM4T(bh, bd);
                    LDSM4T(bl, bd + BSZ);
                }
                #pragma unroll
                for (int i = 0; i < 4; i++)
                    #pragma unroll
                    for (int jj = 0; jj < 2; jj++) {
                        const int j = p * 2 + jj;
                        MMA(acc[i][j], ah[i], bh[jj * 2], bh[jj * 2 + 1]);
                        MMA(acc[i][j], ah[i], bl[jj * 2], bl[jj * 2 + 1]);
                        MMA(acc[i][j], al[i], bh[jj * 2], bh[jj * 2 + 1]);
                    }
            }
        }
    };

    const int NSt = K / BK;
    issue(0); CPCOMMIT();
    issue(1); CPCOMMIT();
    for (int s = 0; s < NSt; s++) {
        CPWAIT1();              /* stage s landed */
        __syncthreads();        /* all warps done with stage s-1 reads */
        if (s + 2 < NSt) issue(s + 2);
        CPCOMMIT();
        compute(s);
    }

    /* ---- epilogue ---- */
    const int* mk = mask ? (mask + (size_t)z * SEQ) : (const int*)0;
    float* Cfz = Cf ? (Cf + z * sC) : (float*)0;
    bf16*  Chz = Ch ? (Ch + z * sC) : (bf16*)0;
    bf16*  Clz = Cl ? (Cl + z * sC) : (bf16*)0;
    const float* rz = res ? (res + z * sC) : (const float*)0;

    #pragma unroll
    for (int i = 0; i < 4; i++) {
        const int r0 = bm + wm * 64 + i * 16 + (lane >> 2);
        #pragma unroll
        for (int j = 0; j < 8; j++) {
            const int c = bn + wn * 64 + j * 8 + ((lane & 3) << 1);
            float ax = acc[i][j][0], ay = acc[i][j][1];
            float az = acc[i][j][2], aw = acc[i][j][3];
            if (mk) {
                const float mc0 = (float)mk[c], mc1 = (float)mk[c + 1];
                const float m0 = (float)mk[r0], m1 = (float)mk[r0 + 8];
                ax = ax * SCALE_QK - (1.f - m0 * mc0) * 1e12f;
                ay = ay * SCALE_QK - (1.f - m0 * mc1) * 1e12f;
                az = az * SCALE_QK - (1.f - m1 * mc0) * 1e12f;
                aw = aw * SCALE_QK - (1.f - m1 * mc1) * 1e12f;
            } else {
                if (bias) {
                    const float b0 = bias[c], b1 = bias[c + 1];
                    ax += b0; ay += b1; az += b0; aw += b1;
                }
                if (relu) {
                    ax = fmaxf(ax, 0.f); ay = fmaxf(ay, 0.f);
                    az = fmaxf(az, 0.f); aw = fmaxf(aw, 0.f);
                }
                if (rz) {
                    const float2 q0 = *(const float2*)&rz[(size_t)r0 * ldc + c];
                    const float2 q1 = *(const float2*)&rz[(size_t)(r0 + 8) * ldc + c];
                    ax += q0.x; ay += q0.y; az += q1.x; aw += q1.y;
                }
            }
            const size_t o0 = (size_t)r0 * ldc + c, o1 = o0 + (size_t)8 * ldc;
            if (Cfz) {
                *(float2*)&Cfz[o0] = make_float2(ax, ay);
                *(float2*)&Cfz[o1] = make_float2(az, aw);
            }
            if (Chz) {
                uint32_t h, l;
                split2(ax, ay, h, l);
                *(uint32_t*)((char*)Chz + o0 * 2) = h;
                *(uint32_t*)((char*)Clz + o0 * 2) = l;
                split2(az, aw, h, l);
                *(uint32_t*)((char*)Chz + o1 * 2) = h;
                *(uint32_t*)((char*)Clz + o1 * 2) = l;
            }
        }
    }
}

/* ---- row softmax, fp32 in -> bf16 hi/lo out, fused mask ---- */
__global__ __launch_bounds__(256) void softmax_kernel(
    const float* __restrict__ Sc, bf16* __restrict__ Wh, bf16* __restrict__ Wl,
    const int* __restrict__ mask)
{
    const int b = blockIdx.y, row = blockIdx.x, tid = threadIdx.x;
    const float* srow = Sc + ((size_t)b * SEQ + row) * SEQ;
    const int* mrow = mask + (size_t)b * SEQ;
    float4 x = *(const float4*)(srow + tid * 4);

    float mx = fmaxf(fmaxf(x.x, x.y), fmaxf(x.z, x.w));
    #pragma unroll
    for (int o = 16; o > 0; o >>= 1) mx = fmaxf(mx, __shfl_xor_sync(~0u, mx, o));
    __shared__ float red[8];
    if ((tid & 31) == 0) red[tid >> 5] = mx;
    __syncthreads();
    float rmx = red[0];
    #pragma unroll
    for (int i = 1; i < 8; i++) rmx = fmaxf(rmx, red[i]);

    float e0 = expf(x.x - rmx), e1 = expf(x.y - rmx);
    float e2 = expf(x.z - rmx), e3 = expf(x.w - rmx);
    float s = e0 + e1 + e2 + e3;
    #pragma unroll
    for (int o = 16; o > 0; o >>= 1) s += __shfl_xor_sync(~0u, s, o);
    __syncthreads();
    if ((tid & 31) == 0) red[tid >> 5] = s;
    __syncthreads();
    float tot = red[0];
    #pragma unroll
    for (int i = 1; i < 8; i++) tot += red[i];

    const float cns = (1.0f / tot) * (float)mrow[row];
    const float o0 = e0 * cns * (float)mrow[tid * 4 + 0];
    const float o1 = e1 * cns * (float)mrow[tid * 4 + 1];
    const float o2 = e2 * cns * (float)mrow[tid * 4 + 2];
    const float o3 = e3 * cns * (float)mrow[tid * 4 + 3];

    uint32_t h0, l0, h1, l1;
    split2(o0, o1, h0, l0);
    split2(o2, o3, h1, l1);
    const size_t off = (((size_t)b * SEQ + row) * SEQ + tid * 4) * 2;
    *(uint2*)((char*)Wh + off) = make_uint2(h0, h1);
    *(uint2*)((char*)Wl + off) = make_uint2(l0, l1);
}

/* --------------------------------------------------------------------- */
extern "C" void kernel_launch(void* const* d_in, const int* in_sizes, int n_in,
                              void* d_out, int out_size)
{
    const float* x    = (const float*)d_in[0];
    const int*   mask = (const int*)  d_in[1];
    const float* Wq = (const float*)d_in[2];
    const float* bq = (const float*)d_in[3];
    const float* Wk = (const float*)d_in[4];
    const float* bk = (const float*)d_in[5];
    const float* Wv = (const float*)d_in[6];
    const float* bv = (const float*)d_in[7];
    const float* W1 = (const float*)d_in[8];
    const float* b1 = (const float*)d_in[9];
    const float* W2 = (const float*)d_in[10];
    const float* b2 = (const float*)d_in[11];
    float* out = (float*)d_out;

    bf16 *xh,*xl,*qh,*ql,*kh,*kl,*vh,*vl,*oh,*ol,*h1h,*h1l;
    bf16 *wqh,*wql,*wkh,*wkl,*wvh,*wvl,*w1h,*w1l,*w2h,*w2l,*wh,*wl;
    float *sc, *of;
    cudaGetSymbolAddress((void**)&xh,  g_xh);  cudaGetSymbolAddress((void**)&xl,  g_xl);
    cudaGetSymbolAddress((void**)&qh,  g_qh);  cudaGetSymbolAddress((void**)&ql,  g_ql);
    cudaGetSymbolAddress((void**)&kh,  g_kh);  cudaGetSymbolAddress((void**)&kl,  g_kl);
    cudaGetSymbolAddress((void**)&vh,  g_vh);  cudaGetSymbolAddress((void**)&vl,  g_vl);
    cudaGetSymbolAddress((void**)&oh,  g_oh);  cudaGetSymbolAddress((void**)&ol,  g_ol);
    cudaGetSymbolAddress((void**)&h1h, g_h1h); cudaGetSymbolAddress((void**)&h1l, g_h1l);
    cudaGetSymbolAddress((void**)&wqh, g_wqh); cudaGetSymbolAddress((void**)&wql, g_wql);
    cudaGetSymbolAddress((void**)&wkh, g_wkh); cudaGetSymbolAddress((void**)&wkl, g_wkl);
    cudaGetSymbolAddress((void**)&wvh, g_wvh); cudaGetSymbolAddress((void**)&wvl, g_wvl);
    cudaGetSymbolAddress((void**)&w1h, g_w1h); cudaGetSymbolAddress((void**)&w1l, g_w1l);
    cudaGetSymbolAddress((void**)&w2h, g_w2h); cudaGetSymbolAddress((void**)&w2l, g_w2l);
    cudaGetSymbolAddress((void**)&wh,  g_wh);  cudaGetSymbolAddress((void**)&wl,  g_wl);
    cudaGetSymbolAddress((void**)&sc,  g_sc);
    cudaGetSymbolAddress((void**)&of,  g_of);

    cudaFuncSetAttribute(gemm_bf, cudaFuncAttributeMaxDynamicSharedMemorySize, SMEM_GEMM);

    /* pre-convert x and weights to bf16 hi/lo */
    cvt_kernel<<<(NXE/2 + 255)/256, 256>>>(x,  (uint32_t*)xh,  (uint32_t*)xl,  NXE/2);
    cvt_kernel<<<(NWE/2 + 255)/256, 256>>>(Wq, (uint32_t*)wqh, (uint32_t*)wql, NWE/2);
    cvt_kernel<<<(NWE/2 + 255)/256, 256>>>(Wk, (uint32_t*)wkh, (uint32_t*)wkl, NWE/2);
    cvt_kernel<<<(NWE/2 + 255)/256, 256>>>(Wv, (uint32_t*)wvh, (uint32_t*)wvl, NWE/2);
    cvt_kernel<<<(NWE/2 + 255)/256, 256>>>(W1, (uint32_t*)w1h, (uint32_t*)w1l, NWE/2);
    cvt_kernel<<<(NWE/2 + 255)/256, 256>>>(W2, (uint32_t*)w2h, (uint32_t*)w2l, NWE/2);

    dim3 blk(NTHREADS);
    const size_t sBH = (size_t)SEQ * HID, sBS = (size_t)SEQ * SEQ;
    dim3 gproj(HID / BN, (NB * SEQ) / BM, 1);   /* (3, 128) */
    dim3 gsc(SEQ / BN, SEQ / BM, NB);           /* (4, 8, 16) */
    dim3 gpv(HID / BN, SEQ / BM, NB);           /* (3, 8, 16) */

    /* q,k,v projections (NT vs weights) */
    gemm_bf<<<gproj, blk, SMEM_GEMM>>>(xh, xl, wqh, wql, HID, 0, 0, 0, 0, 0,
        nullptr, qh, ql, HID, bq, nullptr, nullptr, 1);
    gemm_bf<<<gproj, blk, SMEM_GEMM>>>(xh, xl, wkh, wkl, HID, 0, 0, 0, 0, 0,
        nullptr, kh, kl, HID, bk, nullptr, nullptr, 1);
    gemm_bf<<<gproj, blk, SMEM_GEMM>>>(xh, xl, wvh, wvl, HID, 0, 0, 0, 0, 0,
        nullptr, vh, vl, HID, bv, nullptr, nullptr, 0);

    /* scores = q k^T * scale - mask penalty (fp32 out) */
    gemm_bf<<<gsc, blk, SMEM_GEMM>>>(qh, ql, kh, kl, HID, 0, 0, sBH, sBH, sBS,
        sc, nullptr, nullptr, SEQ, nullptr, nullptr, mask, 0);

    softmax_kernel<<<dim3(SEQ, NB), 256>>>(sc, wh, wl, mask);

    /* O = W V  (NN: B = v[t][h]) */
    gemm_bf<<<gpv, blk, SMEM_GEMM>>>(wh, wl, vh, vl, SEQ, 1, HID, sBS, sBH, sBH,
        of, oh, ol, HID, nullptr, nullptr, nullptr, 0);

    /* FFN */
    gemm_bf<<<gproj, blk, SMEM_GEMM>>>(oh, ol, w1h, w1l, HID, 0, 0, 0, 0, 0,
        nullptr, h1h, h1l, HID, b1, nullptr, nullptr, 1);
    gemm_bf<<<gproj, blk, SMEM_GEMM>>>(h1h, h1l, w2h, w2l, HID, 0, 0, 0, 0, 0,
        out, nullptr, nullptr, HID, b2, of, nullptr, 0);
}

// round 7
// speedup vs baseline: 1.0737x; 1.0737x over previous
#include <cuda_runtime.h>
#include <cuda_bf16.h>
#include <cstdint>

#define NB   16
#define SEQ  1024
#define HID  768
#define SCALE_QK 0.03608439182435161f

#define BM 128
#define BN 128
#define BK 32
#define NTHREADS 128
#define STG 10240            /* bytes per hi or lo tile buffer */
#define STAGE_BYTES 40960    /* Ah,Al,Bh,Bl */
#define NSTAGES 2
#define SMEM_GEMM (NSTAGES*STAGE_BYTES)

typedef __nv_bfloat16 bf16;

/* ------------------ scratch (device globals) ------------------ */
#define NXE 12582912   /* 16*1024*768 */
#define NWE 589824     /* 768*768 */
#define NSE 16777216   /* 16*1024*1024 */
__device__ bf16 g_xh[NXE],  g_xl[NXE];
__device__ bf16 g_qh[NXE],  g_ql[NXE];
__device__ bf16 g_kh[NXE],  g_kl[NXE];
__device__ bf16 g_vh[NXE],  g_vl[NXE];
__device__ bf16 g_oh[NXE],  g_ol[NXE];
__device__ bf16 g_h1h[NXE], g_h1l[NXE];
__device__ bf16 g_wqh[NWE], g_wql[NWE], g_wkh[NWE], g_wkl[NWE], g_wvh[NWE], g_wvl[NWE];
__device__ bf16 g_w1h[NWE], g_w1l[NWE], g_w2h[NWE], g_w2l[NWE];
__device__ float g_sc[NSE];
__device__ bf16 g_wh[NSE],  g_wl[NSE];
__device__ float g_of[NXE];

/* ------------------ helpers ------------------ */
static __device__ __forceinline__ uint32_t smem_u32(const void* p) {
    uint32_t a;
    asm("{ .reg .u64 t; cvta.to.shared.u64 t, %1; cvt.u32.u64 %0, t; }" : "=r"(a) : "l"(p));
    return a;
}
static __device__ __forceinline__ uint32_t pack_bf2(float v0, float v1) {
    uint32_t d;  /* memory order v0,v1 */
    asm("cvt.rn.bf16x2.f32 %0, %1, %2;" : "=r"(d) : "f"(v1), "f"(v0));
    return d;
}
static __device__ __forceinline__ void split2(float v0, float v1, uint32_t& h, uint32_t& l) {
    h = pack_bf2(v0, v1);
    float h0 = __uint_as_float(h << 16);
    float h1 = __uint_as_float(h & 0xFFFF0000u);
    l = pack_bf2(v0 - h0, v1 - h1);
}

#define CP16(dst, src) \
    asm volatile("cp.async.cg.shared.global [%0], [%1], 16;" :: "r"(dst), "l"(src))
#define CPCOMMIT() asm volatile("cp.async.commit_group;" ::: "memory")
#define CPWAIT1()  asm volatile("cp.async.wait_group 1;" ::: "memory")

#define LDSM4(r, a) \
    asm volatile("ldmatrix.sync.aligned.m8n8.x4.shared.b16 {%0,%1,%2,%3}, [%4];" \
        : "=r"((r)[0]),"=r"((r)[1]),"=r"((r)[2]),"=r"((r)[3]) : "r"(a))
#define LDSM4T(r, a) \
    asm volatile("ldmatrix.sync.aligned.m8n8.x4.trans.shared.b16 {%0,%1,%2,%3}, [%4];" \
        : "=r"((r)[0]),"=r"((r)[1]),"=r"((r)[2]),"=r"((r)[3]) : "r"(a))
#define MMA(c, a, b0, b1) \
    asm volatile("mma.sync.aligned.m16n8k16.row.col.f32.bf16.bf16.f32 " \
        "{%0,%1,%2,%3}, {%4,%5,%6,%7}, {%8,%9}, {%0,%1,%2,%3};" \
        : "+f"((c)[0]), "+f"((c)[1]), "+f"((c)[2]), "+f"((c)[3]) \
        : "r"((a)[0]),"r"((a)[1]),"r"((a)[2]),"r"((a)[3]), "r"(b0), "r"(b1))

/* fp32 -> bf16 hi/lo conversion (pre-pass) */
__global__ __launch_bounds__(256) void cvt_kernel(
    const float* __restrict__ in, uint32_t* __restrict__ oh,
    uint32_t* __restrict__ ol, int n2)
{
    int i = blockIdx.x * 256 + threadIdx.x;
    if (i < n2) {
        float2 v = reinterpret_cast<const float2*>(in)[i];
        uint32_t h, l; split2(v.x, v.y, h, l);
        oh[i] = h; ol[i] = l;
    }
}

/* ---------------------------------------------------------------------------
 * bf16 split GEMM, mma.sync m16n8k16.
 * CTA tile 128x128xBK32, 4 warps in 2(m) x 2(n), warp tile 64x64.
 * 2-stage cp.async pipeline, 2 CTAs/SM.
 * nn=0: C = A[M,K] * B[N,K]^T ; nn=1: C = A[M,K] * B[K,N] (ldbn row stride).
 * ------------------------------------------------------------------------ */
__global__ __launch_bounds__(NTHREADS, 2) void gemm_bf(
    const bf16* __restrict__ Ah, const bf16* __restrict__ Al,
    const bf16* __restrict__ Bh, const bf16* __restrict__ Bl,
    int K, int nn, int ldbn,
    size_t sA, size_t sB, size_t sC,
    float* __restrict__ Cf, bf16* __restrict__ Ch, bf16* __restrict__ Cl,
    int ldc, const float* __restrict__ bias, const float* __restrict__ res,
    const int* __restrict__ mask, int relu)
{
    extern __shared__ char smraw[];
    const uint32_t sb = smem_u32(smraw);
    const int tid = threadIdx.x, lane = tid & 31, wid = tid >> 5;
    const int wm = wid & 1, wn = wid >> 1;            /* 2 x 2 warp grid */
    const int z = blockIdx.z, bm = blockIdx.y * BM, bn = blockIdx.x * BN;

    const bf16* Ahg = Ah + z * sA + (size_t)bm * K;
    const bf16* Alg = Al + z * sA + (size_t)bm * K;
    const bf16 *Bhg, *Blg;
    if (nn) { Bhg = Bh + z * sB + bn;              Blg = Bl + z * sB + bn; }
    else    { Bhg = Bh + z * sB + (size_t)bn * K;  Blg = Bl + z * sB + (size_t)bn * K; }

    float acc[4][8][4];
    #pragma unroll
    for (int i = 0; i < 4; i++)
        #pragma unroll
        for (int j = 0; j < 8; j++)
            #pragma unroll
            for (int t = 0; t < 4; t++) acc[i][j][t] = 0.f;

    auto issue = [&](int s) {
        const uint32_t stb = sb + (uint32_t)(s & 1) * STAGE_BYTES;
        const int k0 = s * BK;
        /* A: 128 rows x 32 cols (hi+lo) */
        #pragma unroll
        for (int i = 0; i < 4; i++) {
            const int idx = tid + (i << 7);
            const int row = idx >> 2, c8 = (idx & 3) << 3;
            const uint32_t da = stb + row * 80 + (c8 << 1);
            CP16(da,       Ahg + (size_t)row * K + k0 + c8);
            CP16(da + STG, Alg + (size_t)row * K + k0 + c8);
        }
        if (!nn) {
            #pragma unroll
            for (int i = 0; i < 4; i++) {
                const int idx = tid + (i << 7);
                const int row = idx >> 2, c8 = (idx & 3) << 3;
                const uint32_t db = stb + 2 * STG + row * 80 + (c8 << 1);
                CP16(db,       Bhg + (size_t)row * K + k0 + c8);
                CP16(db + STG, Blg + (size_t)row * K + k0 + c8);
            }
        } else {
            /* B: 32 rows x 128 cols, N-major, row stride 272 */
            #pragma unroll
            for (int i = 0; i < 4; i++) {
                const int idx = tid + (i << 7);
                const int row = idx >> 4, c8 = (idx & 15) << 3;
                const uint32_t db = stb + 2 * STG + row * 272 + (c8 << 1);
                CP16(db,       Bhg + (size_t)(k0 + row) * ldbn + c8);
                CP16(db + STG, Blg + (size_t)(k0 + row) * ldbn + c8);
            }
        }
    };

    auto compute = [&](int s) {
        const uint32_t stb = sb + (uint32_t)(s & 1) * STAGE_BYTES;
        #pragma unroll
        for (int ks = 0; ks < 2; ks++) {
            uint32_t ah[4][4], al[4][4];
            #pragma unroll
            for (int i = 0; i < 4; i++) {
                const int arow = wm * 64 + i * 16 + (lane & 15);
                const uint32_t ad = stb + arow * 80 + ((ks * 16 + ((lane >> 4) << 3)) << 1);
                LDSM4(ah[i], ad);
                LDSM4(al[i], ad + STG);
            }
            #pragma unroll
            for (int p = 0; p < 4; p++) {
                uint32_t bh[4], bl[4];
                if (!nn) {
                    const int brow = wn * 64 + p * 16 + (lane & 7) + ((lane >> 4) << 3);
                    const uint32_t bd = stb + 2 * STG + brow * 80 +
                                        ((ks * 16 + (((lane >> 3) & 1) << 3)) << 1);
                    LDSM4(bh, bd);
                    LDSM4(bl, bd + STG);
                } else {
                    const int krow = ks * 16 + (lane & 7) + (((lane >> 3) & 1) << 3);
                    const int ncol = wn * 64 + p * 16 + ((lane >> 4) << 3);
                    const uint32_t bd = stb + 2 * STG + krow * 272 + (ncol << 1);
                    LDSM4T(bh, bd);
                    LDSM4T(bl, bd + STG);
                }
                #pragma unroll
                for (int i = 0; i < 4; i++)
                    #pragma unroll
                    for (int jj = 0; jj < 2; jj++) {
                        const int j = p * 2 + jj;
                        MMA(acc[i][j], ah[i], bh[jj * 2], bh[jj * 2 + 1]);
                        MMA(acc[i][j], ah[i], bl[jj * 2], bl[jj * 2 + 1]);
                        MMA(acc[i][j], al[i], bh[jj * 2], bh[jj * 2 + 1]);
                    }
            }
        }
    };

    const int NSt = K / BK;
    issue(0); CPCOMMIT();
    for (int s = 0; s < NSt; s++) {
        if (s + 1 < NSt) issue(s + 1);
        CPCOMMIT();
        CPWAIT1();
        __syncthreads();
        compute(s);
        __syncthreads();
    }

    /* ---- epilogue ---- */
    const int* mk = mask ? (mask + (size_t)z * SEQ) : (const int*)0;
    float* Cfz = Cf ? (Cf + z * sC) : (float*)0;
    bf16*  Chz = Ch ? (Ch + z * sC) : (bf16*)0;
    bf16*  Clz = Cl ? (Cl + z * sC) : (bf16*)0;
    const float* rz = res ? (res + z * sC) : (const float*)0;

    #pragma unroll
    for (int i = 0; i < 4; i++) {
        const int r0 = bm + wm * 64 + i * 16 + (lane >> 2);
        #pragma unroll
        for (int j = 0; j < 8; j++) {
            const int c = bn + wn * 64 + j * 8 + ((lane & 3) << 1);
            float ax = acc[i][j][0], ay = acc[i][j][1];
            float az = acc[i][j][2], aw = acc[i][j][3];
            if (mk) {
                const float mc0 = (float)mk[c], mc1 = (float)mk[c + 1];
                const float m0 = (float)mk[r0], m1 = (float)mk[r0 + 8];
                ax = ax * SCALE_QK - (1.f - m0 * mc0) * 1e12f;
                ay = ay * SCALE_QK - (1.f - m0 * mc1) * 1e12f;
                az = az * SCALE_QK - (1.f - m1 * mc0) * 1e12f;
                aw = aw * SCALE_QK - (1.f - m1 * mc1) * 1e12f;
            } else {
                if (bias) {
                    const float b0 = bias[c], b1 = bias[c + 1];
                    ax += b0; ay += b1; az += b0; aw += b1;
                }
                if (relu) {
                    ax = fmaxf(ax, 0.f); ay = fmaxf(ay, 0.f);
                    az = fmaxf(az, 0.f); aw = fmaxf(aw, 0.f);
                }
                if (rz) {
                    const float2 q0 = *(const float2*)&rz[(size_t)r0 * ldc + c];
                    const float2 q1 = *(const float2*)&rz[(size_t)(r0 + 8) * ldc + c];
                    ax += q0.x; ay += q0.y; az += q1.x; aw += q1.y;
                }
            }
            const size_t o0 = (size_t)r0 * ldc + c, o1 = o0 + (size_t)8 * ldc;
            if (Cfz) {
                *(float2*)&Cfz[o0] = make_float2(ax, ay);
                *(float2*)&Cfz[o1] = make_float2(az, aw);
            }
            if (Chz) {
                uint32_t h, l;
                split2(ax, ay, h, l);
                *(uint32_t*)((char*)Chz + o0 * 2) = h;
                *(uint32_t*)((char*)Clz + o0 * 2) = l;
                split2(az, aw, h, l);
                *(uint32_t*)((char*)Chz + o1 * 2) = h;
                *(uint32_t*)((char*)Clz + o1 * 2) = l;
            }
        }
    }
}

/* ---- row softmax, fp32 in -> bf16 hi/lo out, fused mask ---- */
__global__ __launch_bounds__(256) void softmax_kernel(
    const float* __restrict__ Sc, bf16* __restrict__ Wh, bf16* __restrict__ Wl,
    const int* __restrict__ mask)
{
    const int b = blockIdx.y, row = blockIdx.x, tid = threadIdx.x;
    const float* srow = Sc + ((size_t)b * SEQ + row) * SEQ;
    const int* mrow = mask + (size_t)b * SEQ;
    float4 x = *(const float4*)(srow + tid * 4);

    float mx = fmaxf(fmaxf(x.x, x.y), fmaxf(x.z, x.w));
    #pragma unroll
    for (int o = 16; o > 0; o >>= 1) mx = fmaxf(mx, __shfl_xor_sync(~0u, mx, o));
    __shared__ float red[8];
    if ((tid & 31) == 0) red[tid >> 5] = mx;
    __syncthreads();
    float rmx = red[0];
    #pragma unroll
    for (int i = 1; i < 8; i++) rmx = fmaxf(rmx, red[i]);

    float e0 = expf(x.x - rmx), e1 = expf(x.y - rmx);
    float e2 = expf(x.z - rmx), e3 = expf(x.w - rmx);
    float s = e0 + e1 + e2 + e3;
    #pragma unroll
    for (int o = 16; o > 0; o >>= 1) s += __shfl_xor_sync(~0u, s, o);
    __syncthreads();
    if ((tid & 31) == 0) red[tid >> 5] = s;
    __syncthreads();
    float tot = red[0];
    #pragma unroll
    for (int i = 1; i < 8; i++) tot += red[i];

    const float cns = (1.0f / tot) * (float)mrow[row];
    const float o0 = e0 * cns * (float)mrow[tid * 4 + 0];
    const float o1 = e1 * cns * (float)mrow[tid * 4 + 1];
    const float o2 = e2 * cns * (float)mrow[tid * 4 + 2];
    const float o3 = e3 * cns * (float)mrow[tid * 4 + 3];

    uint32_t h0, l0, h1, l1;
    split2(o0, o1, h0, l0);
    split2(o2, o3, h1, l1);
    const size_t off = (((size_t)b * SEQ + row) * SEQ + tid * 4) * 2;
    *(uint2*)((char*)Wh + off) = make_uint2(h0, h1);
    *(uint2*)((char*)Wl + off) = make_uint2(l0, l1);
}

/* --------------------------------------------------------------------- */
extern "C" void kernel_launch(void* const* d_in, const int* in_sizes, int n_in,
                              void* d_out, int out_size)
{
    const float* x    = (const float*)d_in[0];
    const int*   mask = (const int*)  d_in[1];
    const float* Wq = (const float*)d_in[2];
    const float* bq = (const float*)d_in[3];
    const float* Wk = (const float*)d_in[4];
    const float* bk = (const float*)d_in[5];
    const float* Wv = (const float*)d_in[6];
    const float* bv = (const float*)d_in[7];
    const float* W1 = (const float*)d_in[8];
    const float* b1 = (const float*)d_in[9];
    const float* W2 = (const float*)d_in[10];
    const float* b2 = (const float*)d_in[11];
    float* out = (float*)d_out;

    bf16 *xh,*xl,*qh,*ql,*kh,*kl,*vh,*vl,*oh,*ol,*h1h,*h1l;
    bf16 *wqh,*wql,*wkh,*wkl,*wvh,*wvl,*w1h,*w1l,*w2h,*w2l,*wh,*wl;
    float *sc, *of;
    cudaGetSymbolAddress((void**)&xh,  g_xh);  cudaGetSymbolAddress((void**)&xl,  g_xl);
    cudaGetSymbolAddress((void**)&qh,  g_qh);  cudaGetSymbolAddress((void**)&ql,  g_ql);
    cudaGetSymbolAddress((void**)&kh,  g_kh);  cudaGetSymbolAddress((void**)&kl,  g_kl);
    cudaGetSymbolAddress((void**)&vh,  g_vh);  cudaGetSymbolAddress((void**)&vl,  g_vl);
    cudaGetSymbolAddress((void**)&oh,  g_oh);  cudaGetSymbolAddress((void**)&ol,  g_ol);
    cudaGetSymbolAddress((void**)&h1h, g_h1h); cudaGetSymbolAddress((void**)&h1l, g_h1l);
    cudaGetSymbolAddress((void**)&wqh, g_wqh); cudaGetSymbolAddress((void**)&wql, g_wql);
    cudaGetSymbolAddress((void**)&wkh, g_wkh); cudaGetSymbolAddress((void**)&wkl, g_wkl);
    cudaGetSymbolAddress((void**)&wvh, g_wvh); cudaGetSymbolAddress((void**)&wvl, g_wvl);
    cudaGetSymbolAddress((void**)&w1h, g_w1h); cudaGetSymbolAddress((void**)&w1l, g_w1l);
    cudaGetSymbolAddress((void**)&w2h, g_w2h); cudaGetSymbolAddress((void**)&w2l, g_w2l);
    cudaGetSymbolAddress((void**)&wh,  g_wh);  cudaGetSymbolAddress((void**)&wl,  g_wl);
    cudaGetSymbolAddress((void**)&sc,  g_sc);
    cudaGetSymbolAddress((void**)&of,  g_of);

    cudaFuncSetAttribute(gemm_bf, cudaFuncAttributeMaxDynamicSharedMemorySize, SMEM_GEMM);

    dim3 blk(NTHREADS);
    const size_t sBH = (size_t)SEQ * HID, sBS = (size_t)SEQ * SEQ;
    dim3 gproj(HID / BN, (NB * SEQ) / BM, 1);   /* (6, 128) */
    dim3 gsc(SEQ / BN, SEQ / BM, NB);           /* (8, 8, 16) */
    dim3 gpv(HID / BN, SEQ / BM, NB);           /* (6, 8, 16) */

    /* 5 cvt launches first so the 6th launch (ncu -s 5 -c 1) is a gemm_bf */
    cvt_kernel<<<(NXE/2 + 255)/256, 256>>>(x,  (uint32_t*)xh,  (uint32_t*)xl,  NXE/2);
    cvt_kernel<<<(NWE/2 + 255)/256, 256>>>(Wq, (uint32_t*)wqh, (uint32_t*)wql, NWE/2);
    cvt_kernel<<<(NWE/2 + 255)/256, 256>>>(Wk, (uint32_t*)wkh, (uint32_t*)wkl, NWE/2);
    cvt_kernel<<<(NWE/2 + 255)/256, 256>>>(Wv, (uint32_t*)wvh, (uint32_t*)wvl, NWE/2);
    cvt_kernel<<<(NWE/2 + 255)/256, 256>>>(W1, (uint32_t*)w1h, (uint32_t*)w1l, NWE/2);

    /* q projection — launch index 5, captured by ncu */
    gemm_bf<<<gproj, blk, SMEM_GEMM>>>(xh, xl, wqh, wql, HID, 0, 0, 0, 0, 0,
        nullptr, qh, ql, HID, bq, nullptr, nullptr, 1);

    cvt_kernel<<<(NWE/2 + 255)/256, 256>>>(W2, (uint32_t*)w2h, (uint32_t*)w2l, NWE/2);

    gemm_bf<<<gproj, blk, SMEM_GEMM>>>(xh, xl, wkh, wkl, HID, 0, 0, 0, 0, 0,
        nullptr, kh, kl, HID, bk, nullptr, nullptr, 1);
    gemm_bf<<<gproj, blk, SMEM_GEMM>>>(xh, xl, wvh, wvl, HID, 0, 0, 0, 0, 0,
        nullptr, vh, vl, HID, bv, nullptr, nullptr, 0);

    /* scores = q k^T * scale - mask penalty (fp32 out) */
    gemm_bf<<<gsc, blk, SMEM_GEMM>>>(qh, ql, kh, kl, HID, 0, 0, sBH, sBH, sBS,
        sc, nullptr, nullptr, SEQ, nullptr, nullptr, mask, 0);

    softmax_kernel<<<dim3(SEQ, NB), 256>>>(sc, wh, wl, mask);

    /* O = W V  (NN: B = v[t][h]) */
    gemm_bf<<<gpv, blk, SMEM_GEMM>>>(wh, wl, vh, vl, SEQ, 1, HID, sBS, sBH, sBH,
        of, oh, ol, HID, nullptr, nullptr, nullptr, 0);

    /* FFN */
    gemm_bf<<<gproj, blk, SMEM_GEMM>>>(oh, ol, w1h, w1l, HID, 0, 0, 0, 0, 0,
        nullptr, h1h, h1l, HID, b1, nullptr, nullptr, 1);
    gemm_bf<<<gproj, blk, SMEM_GEMM>>>(h1h, h1l, w2h, w2l, HID, 0, 0, 0, 0, 0,
        out, nullptr, nullptr, HID, b2, of, nullptr, 0);
}

// round 8
// speedup vs baseline: 2.7899x; 2.5984x over previous
#include <cuda_runtime.h>
#include <cuda_fp16.h>
#include <cstdint>

#define NB   16
#define SEQ  1024
#define HID  768
#define SCALE_QK 0.03608439182435161f

#define BM 128
#define BN 128
#define BK 32
#define NTHREADS 128
#define STG 10240            /* one operand tile: 128 rows * 80B */
#define STAGE_BYTES 20480    /* A + B */
#define NSTAGES 4
#define SMEM_GEMM (NSTAGES*STAGE_BYTES)   /* 80 KB -> 2 CTAs/SM */

typedef __half fp16;

/* ------------------ scratch (device globals) ------------------ */
#define NXE 12582912   /* 16*1024*768 */
#define NWE 589824     /* 768*768 */
#define NSE 16777216   /* 16*1024*1024 */
__device__ fp16 g_x [NXE];
__device__ fp16 g_q [NXE];
__device__ fp16 g_k [NXE];
__device__ fp16 g_v [NXE];
__device__ fp16 g_o [NXE];
__device__ fp16 g_h1[NXE];
__device__ fp16 g_wq[NWE], g_wk[NWE], g_wv[NWE], g_w1[NWE], g_w2[NWE];
__device__ float g_sc[NSE];
__device__ fp16 g_w [NSE];
__device__ float g_of[NXE];

/* ------------------ helpers ------------------ */
static __device__ __forceinline__ uint32_t smem_u32(const void* p) {
    uint32_t a;
    asm("{ .reg .u64 t; cvta.to.shared.u64 t, %1; cvt.u32.u64 %0, t; }" : "=r"(a) : "l"(p));
    return a;
}
static __device__ __forceinline__ uint32_t pack_h2(float v0, float v1) {
    __half2 h = __floats2half2_rn(v0, v1);   /* v0 -> low half (memory order v0,v1) */
    return *reinterpret_cast<uint32_t*>(&h);
}

#define CP16(dst, src) \
    asm volatile("cp.async.cg.shared.global [%0], [%1], 16;" :: "r"(dst), "l"(src))
#define CPCOMMIT() asm volatile("cp.async.commit_group;" ::: "memory")
#define CPWAIT2()  asm volatile("cp.async.wait_group 2;" ::: "memory")

#define LDSM4(r, a) \
    asm volatile("ldmatrix.sync.aligned.m8n8.x4.shared.b16 {%0,%1,%2,%3}, [%4];" \
        : "=r"((r)[0]),"=r"((r)[1]),"=r"((r)[2]),"=r"((r)[3]) : "r"(a))
#define LDSM4T(r, a) \
    asm volatile("ldmatrix.sync.aligned.m8n8.x4.trans.shared.b16 {%0,%1,%2,%3}, [%4];" \
        : "=r"((r)[0]),"=r"((r)[1]),"=r"((r)[2]),"=r"((r)[3]) : "r"(a))
#define MMA(c, a, b0, b1) \
    asm volatile("mma.sync.aligned.m16n8k16.row.col.f32.f16.f16.f32 " \
        "{%0,%1,%2,%3}, {%4,%5,%6,%7}, {%8,%9}, {%0,%1,%2,%3};" \
        : "+f"((c)[0]), "+f"((c)[1]), "+f"((c)[2]), "+f"((c)[3]) \
        : "r"((a)[0]),"r"((a)[1]),"r"((a)[2]),"r"((a)[3]), "r"(b0), "r"(b1))

/* fp32 -> fp16 conversion (pre-pass) */
__global__ __launch_bounds__(256) void cvt_kernel(
    const float* __restrict__ in, uint32_t* __restrict__ oh, int n2)
{
    int i = blockIdx.x * 256 + threadIdx.x;
    if (i < n2) {
        float2 v = reinterpret_cast<const float2*>(in)[i];
        oh[i] = pack_h2(v.x, v.y);
    }
}

/* ---------------------------------------------------------------------------
 * fp16 GEMM, mma.sync m16n8k16, fp32 accumulate.
 * CTA tile 128x128xBK32, 4 warps (2m x 2n), warp tile 64x64.
 * 4-stage cp.async pipeline, one __syncthreads per stage, 2 CTAs/SM.
 * nn=0: C = A[M,K] * B[N,K]^T ; nn=1: C = A[M,K] * B[K,N] (ldbn row stride).
 * ------------------------------------------------------------------------ */
__global__ __launch_bounds__(NTHREADS, 2) void gemm_fp16(
    const fp16* __restrict__ A, const fp16* __restrict__ B,
    int K, int nn, int ldbn,
    size_t sA, size_t sB, size_t sC,
    float* __restrict__ Cf, fp16* __restrict__ Ch,
    int ldc, const float* __restrict__ bias, const float* __restrict__ res,
    const int* __restrict__ mask, int relu)
{
    extern __shared__ char smraw[];
    const uint32_t sb = smem_u32(smraw);
    const int tid = threadIdx.x, lane = tid & 31, wid = tid >> 5;
    const int wm = wid & 1, wn = wid >> 1;            /* 2 x 2 warp grid */
    const int z = blockIdx.z, bm = blockIdx.y * BM, bn = blockIdx.x * BN;

    const fp16* Ag = A + z * sA + (size_t)bm * K;
    const fp16* Bg;
    if (nn) Bg = B + z * sB + bn;
    else    Bg = B + z * sB + (size_t)bn * K;

    float acc[4][8][4];
    #pragma unroll
    for (int i = 0; i < 4; i++)
        #pragma unroll
        for (int j = 0; j < 8; j++)
            #pragma unroll
            for (int t = 0; t < 4; t++) acc[i][j][t] = 0.f;

    auto issue = [&](int s) {
        const uint32_t stb = sb + (uint32_t)(s % NSTAGES) * STAGE_BYTES;
        const int k0 = s * BK;
        /* A: 128 rows x 32 halves (64B) per stage */
        #pragma unroll
        for (int i = 0; i < 4; i++) {
            const int idx = tid + (i << 7);
            const int row = idx >> 2, c8 = (idx & 3) << 3;
            CP16(stb + row * 80 + (c8 << 1), Ag + (size_t)row * K + k0 + c8);
        }
        if (!nn) {
            #pragma unroll
            for (int i = 0; i < 4; i++) {
                const int idx = tid + (i << 7);
                const int row = idx >> 2, c8 = (idx & 3) << 3;
                CP16(stb + STG + row * 80 + (c8 << 1), Bg + (size_t)row * K + k0 + c8);
            }
        } else {
            /* B: 32 rows x 128 halves, N-major, row stride 272B */
            #pragma unroll
            for (int i = 0; i < 4; i++) {
                const int idx = tid + (i << 7);
                const int row = idx >> 4, c8 = (idx & 15) << 3;
                CP16(stb + STG + row * 272 + (c8 << 1), Bg + (size_t)(k0 + row) * ldbn + c8);
            }
        }
    };

    auto compute = [&](int s) {
        const uint32_t stb = sb + (uint32_t)(s % NSTAGES) * STAGE_BYTES;
        #pragma unroll
        for (int ks = 0; ks < 2; ks++) {
            uint32_t ah[4][4];
            #pragma unroll
            for (int i = 0; i < 4; i++) {
                const int arow = wm * 64 + i * 16 + (lane & 15);
                LDSM4(ah[i], stb + arow * 80 + ((ks * 16 + ((lane >> 4) << 3)) << 1));
            }
            #pragma unroll
            for (int p = 0; p < 4; p++) {
                uint32_t bh[4];
                if (!nn) {
                    const int brow = wn * 64 + p * 16 + (lane & 7) + ((lane >> 4) << 3);
                    LDSM4(bh, stb + STG + brow * 80 +
                              ((ks * 16 + (((lane >> 3) & 1) << 3)) << 1));
                } else {
                    const int krow = ks * 16 + (lane & 7) + (((lane >> 3) & 1) << 3);
                    const int ncol = wn * 64 + p * 16 + ((lane >> 4) << 3);
                    LDSM4T(bh, stb + STG + krow * 272 + (ncol << 1));
                }
                #pragma unroll
                for (int i = 0; i < 4; i++)
                    #pragma unroll
                    for (int jj = 0; jj < 2; jj++)
                        MMA(acc[i][p * 2 + jj], ah[i], bh[jj * 2], bh[jj * 2 + 1]);
            }
        }
    };

    const int NSt = K / BK;
    issue(0); CPCOMMIT();
    issue(1); CPCOMMIT();
    issue(2); CPCOMMIT();
    for (int s = 0; s < NSt; s++) {
        CPWAIT2();              /* stage s landed (<=2 groups still pending) */
        __syncthreads();        /* all warps done reading stage (s+4)%4 target */
        if (s + 3 < NSt) issue(s + 3);
        CPCOMMIT();
        compute(s);
    }

    /* ---- epilogue ---- */
    const int* mk = mask ? (mask + (size_t)z * SEQ) : (const int*)0;
    float* Cfz = Cf ? (Cf + z * sC) : (float*)0;
    fp16*  Chz = Ch ? (Ch + z * sC) : (fp16*)0;
    const float* rz = res ? (res + z * sC) : (const float*)0;

    #pragma unroll
    for (int i = 0; i < 4; i++) {
        const int r0 = bm + wm * 64 + i * 16 + (lane >> 2);
        #pragma unroll
        for (int j = 0; j < 8; j++) {
            const int c = bn + wn * 64 + j * 8 + ((lane & 3) << 1);
            float ax = acc[i][j][0], ay = acc[i][j][1];
            float az = acc[i][j][2], aw = acc[i][j][3];
            if (mk) {
                const float mc0 = (float)mk[c], mc1 = (float)mk[c + 1];
                const float m0 = (float)mk[r0], m1 = (float)mk[r0 + 8];
                ax = ax * SCALE_QK - (1.f - m0 * mc0) * 1e12f;
                ay = ay * SCALE_QK - (1.f - m0 * mc1) * 1e12f;
                az = az * SCALE_QK - (1.f - m1 * mc0) * 1e12f;
                aw = aw * SCALE_QK - (1.f - m1 * mc1) * 1e12f;
            } else {
                if (bias) {
                    const float b0 = bias[c], b1 = bias[c + 1];
                    ax += b0; ay += b1; az += b0; aw += b1;
                }
                if (relu) {
                    ax = fmaxf(ax, 0.f); ay = fmaxf(ay, 0.f);
                    az = fmaxf(az, 0.f); aw = fmaxf(aw, 0.f);
                }
                if (rz) {
                    const float2 q0 = *(const float2*)&rz[(size_t)r0 * ldc + c];
                    const float2 q1 = *(const float2*)&rz[(size_t)(r0 + 8) * ldc + c];
                    ax += q0.x; ay += q0.y; az += q1.x; aw += q1.y;
                }
            }
            const size_t o0 = (size_t)r0 * ldc + c, o1 = o0 + (size_t)8 * ldc;
            if (Cfz) {
                *(float2*)&Cfz[o0] = make_float2(ax, ay);
                *(float2*)&Cfz[o1] = make_float2(az, aw);
            }
            if (Chz) {
                *(uint32_t*)((char*)Chz + o0 * 2) = pack_h2(ax, ay);
                *(uint32_t*)((char*)Chz + o1 * 2) = pack_h2(az, aw);
            }
        }
    }
}

/* ---- row softmax, fp32 in -> fp16 out, fused mask ---- */
__global__ __launch_bounds__(256) void softmax_kernel(
    const float* __restrict__ Sc, fp16* __restrict__ Wout,
    const int* __restrict__ mask)
{
    const int b = blockIdx.y, row = blockIdx.x, tid = threadIdx.x;
    const float* srow = Sc + ((size_t)b * SEQ + row) * SEQ;
    const int* mrow = mask + (size_t)b * SEQ;
    float4 x = *(const float4*)(srow + tid * 4);

    float mx = fmaxf(fmaxf(x.x, x.y), fmaxf(x.z, x.w));
    #pragma unroll
    for (int o = 16; o > 0; o >>= 1) mx = fmaxf(mx, __shfl_xor_sync(~0u, mx, o));
    __shared__ float red[8];
    if ((tid & 31) == 0) red[tid >> 5] = mx;
    __syncthreads();
    float rmx = red[0];
    #pragma unroll
    for (int i = 1; i < 8; i++) rmx = fmaxf(rmx, red[i]);

    float e0 = expf(x.x - rmx), e1 = expf(x.y - rmx);
    float e2 = expf(x.z - rmx), e3 = expf(x.w - rmx);
    float s = e0 + e1 + e2 + e3;
    #pragma unroll
    for (int o = 16; o > 0; o >>= 1) s += __shfl_xor_sync(~0u, s, o);
    __syncthreads();
    if ((tid & 31) == 0) red[tid >> 5] = s;
    __syncthreads();
    float tot = red[0];
    #pragma unroll
    for (int i = 1; i < 8; i++) tot += red[i];

    const float cns = (1.0f / tot) * (float)mrow[row];
    const float o0 = e0 * cns * (float)mrow[tid * 4 + 0];
    const float o1 = e1 * cns * (float)mrow[tid * 4 + 1];
    const float o2 = e2 * cns * (float)mrow[tid * 4 + 2];
    const float o3 = e3 * cns * (float)mrow[tid * 4 + 3];

    const size_t off = (((size_t)b * SEQ + row) * SEQ + tid * 4) * 2;
    *(uint2*)((char*)Wout + off) = make_uint2(pack_h2(o0, o1), pack_h2(o2, o3));
}

/* --------------------------------------------------------------------- */
extern "C" void kernel_launch(void* const* d_in, const int* in_sizes, int n_in,
                              void* d_out, int out_size)
{
    const float* x    = (const float*)d_in[0];
    const int*   mask = (const int*)  d_in[1];
    const float* Wq = (const float*)d_in[2];
    const float* bq = (const float*)d_in[3];
    const float* Wk = (const float*)d_in[4];
    const float* bk = (const float*)d_in[5];
    const float* Wv = (const float*)d_in[6];
    const float* bv = (const float*)d_in[7];
    const float* W1 = (const float*)d_in[8];
    const float* b1 = (const float*)d_in[9];
    const float* W2 = (const float*)d_in[10];
    const float* b2 = (const float*)d_in[11];
    float* out = (float*)d_out;

    fp16 *xh,*qh,*kh,*vh,*oh,*h1h,*wqh,*wkh,*wvh,*w1h,*w2h,*wh;
    float *sc, *of;
    cudaGetSymbolAddress((void**)&xh,  g_x);
    cudaGetSymbolAddress((void**)&qh,  g_q);
    cudaGetSymbolAddress((void**)&kh,  g_k);
    cudaGetSymbolAddress((void**)&vh,  g_v);
    cudaGetSymbolAddress((void**)&oh,  g_o);
    cudaGetSymbolAddress((void**)&h1h, g_h1);
    cudaGetSymbolAddress((void**)&wqh, g_wq);
    cudaGetSymbolAddress((void**)&wkh, g_wk);
    cudaGetSymbolAddress((void**)&wvh, g_wv);
    cudaGetSymbolAddress((void**)&w1h, g_w1);
    cudaGetSymbolAddress((void**)&w2h, g_w2);
    cudaGetSymbolAddress((void**)&wh,  g_w);
    cudaGetSymbolAddress((void**)&sc,  g_sc);
    cudaGetSymbolAddress((void**)&of,  g_of);

    cudaFuncSetAttribute(gemm_fp16, cudaFuncAttributeMaxDynamicSharedMemorySize, SMEM_GEMM);

    dim3 blk(NTHREADS);
    const size_t sBH = (size_t)SEQ * HID, sBS = (size_t)SEQ * SEQ;
    dim3 gproj(HID / BN, (NB * SEQ) / BM, 1);   /* (6, 128) */
    dim3 gsc(SEQ / BN, SEQ / BM, NB);           /* (8, 8, 16) */
    dim3 gpv(HID / BN, SEQ / BM, NB);           /* (6, 8, 16) */

    /* 5 cvt launches first so the 6th launch (ncu -s 5 -c 1) is a gemm */
    cvt_kernel<<<(NXE/2 + 255)/256, 256>>>(x,  (uint32_t*)xh,  NXE/2);
    cvt_kernel<<<(NWE/2 + 255)/256, 256>>>(Wq, (uint32_t*)wqh, NWE/2);
    cvt_kernel<<<(NWE/2 + 255)/256, 256>>>(Wk, (uint32_t*)wkh, NWE/2);
    cvt_kernel<<<(NWE/2 + 255)/256, 256>>>(Wv, (uint32_t*)wvh, NWE/2);
    cvt_kernel<<<(NWE/2 + 255)/256, 256>>>(W1, (uint32_t*)w1h, NWE/2);

    /* q projection — launch index 5, captured by ncu */
    gemm_fp16<<<gproj, blk, SMEM_GEMM>>>(xh, wqh, HID, 0, 0, 0, 0, 0,
        nullptr, qh, HID, bq, nullptr, nullptr, 1);

    cvt_kernel<<<(NWE/2 + 255)/256, 256>>>(W2, (uint32_t*)w2h, NWE/2);

    gemm_fp16<<<gproj, blk, SMEM_GEMM>>>(xh, wkh, HID, 0, 0, 0, 0, 0,
        nullptr, kh, HID, bk, nullptr, nullptr, 1);
    gemm_fp16<<<gproj, blk, SMEM_GEMM>>>(xh, wvh, HID, 0, 0, 0, 0, 0,
        nullptr, vh, HID, bv, nullptr, nullptr, 0);

    /* scores = q k^T * scale - mask penalty (fp32 out) */
    gemm_fp16<<<gsc, blk, SMEM_GEMM>>>(qh, kh, HID, 0, 0, sBH, sBH, sBS,
        sc, nullptr, SEQ, nullptr, nullptr, mask, 0);

    softmax_kernel<<<dim3(SEQ, NB), 256>>>(sc, wh, mask);

    /* O = W V  (NN: B = v[t][h]) */
    gemm_fp16<<<gpv, blk, SMEM_GEMM>>>(wh, vh, SEQ, 1, HID, sBS, sBH, sBH,
        of, oh, HID, nullptr, nullptr, nullptr, 0);

    /* FFN */
    gemm_fp16<<<gproj, blk, SMEM_GEMM>>>(oh, w1h, HID, 0, 0, 0, 0, 0,
        nullptr, h1h, HID, b1, nullptr, nullptr, 1);
    gemm_fp16<<<gproj, blk, SMEM_GEMM>>>(h1h, w2h, HID, 0, 0, 0, 0, 0,
        out, nullptr, HID, b2, of, nullptr, 0);
}

// round 9
// speedup vs baseline: 2.9952x; 1.0736x over previous
#include <cuda_runtime.h>
#include <cuda_fp16.h>
#include <cstdint>

#define NB   16
#define SEQ  1024
#define HID  768
#define SCALE_QK 0.03608439182435161f

#define BM 128
#define BN 128
#define BK 32
#define NTHREADS 128
#define STG 10240            /* one operand tile: 128 rows * 80B */
#define STAGE_BYTES 20480    /* A + B */
#define NSTAGES 4
#define SMEM_GEMM (NSTAGES*STAGE_BYTES)   /* 80 KB -> 2 CTAs/SM */

typedef __half fp16;

/* ------------------ scratch (device globals) ------------------ */
#define NXE 12582912   /* 16*1024*768 */
#define NWE 589824     /* 768*768 */
#define NSE 16777216   /* 16*1024*1024 */
__device__ fp16 g_x [NXE];
__device__ fp16 g_q [NXE];
__device__ fp16 g_k [NXE];
__device__ fp16 g_v [NXE];
__device__ fp16 g_o [NXE];
__device__ fp16 g_h1[NXE];
__device__ fp16 g_wqkv[3*NWE];            /* [Wq;Wk;Wv] each [768,768] K-major */
__device__ fp16 g_w1[NWE], g_w2[NWE];
__device__ float g_sc[NSE];
__device__ fp16 g_w [NSE];

/* ------------------ helpers ------------------ */
static __device__ __forceinline__ uint32_t smem_u32(const void* p) {
    uint32_t a;
    asm("{ .reg .u64 t; cvta.to.shared.u64 t, %1; cvt.u32.u64 %0, t; }" : "=r"(a) : "l"(p));
    return a;
}
static __device__ __forceinline__ uint32_t pack_h2(float v0, float v1) {
    __half2 h = __floats2half2_rn(v0, v1);   /* v0 -> low half (memory order v0,v1) */
    return *reinterpret_cast<uint32_t*>(&h);
}

#define CP16(dst, src) \
    asm volatile("cp.async.cg.shared.global [%0], [%1], 16;" :: "r"(dst), "l"(src))
#define CPCOMMIT() asm volatile("cp.async.commit_group;" ::: "memory")
#define CPWAIT2()  asm volatile("cp.async.wait_group 2;" ::: "memory")

#define LDSM4(r, a) \
    asm volatile("ldmatrix.sync.aligned.m8n8.x4.shared.b16 {%0,%1,%2,%3}, [%4];" \
        : "=r"((r)[0]),"=r"((r)[1]),"=r"((r)[2]),"=r"((r)[3]) : "r"(a))
#define LDSM4T(r, a) \
    asm volatile("ldmatrix.sync.aligned.m8n8.x4.trans.shared.b16 {%0,%1,%2,%3}, [%4];" \
        : "=r"((r)[0]),"=r"((r)[1]),"=r"((r)[2]),"=r"((r)[3]) : "r"(a))
#define MMA(c, a, b0, b1) \
    asm volatile("mma.sync.aligned.m16n8k16.row.col.f32.f16.f16.f32 " \
        "{%0,%1,%2,%3}, {%4,%5,%6,%7}, {%8,%9}, {%0,%1,%2,%3};" \
        : "+f"((c)[0]), "+f"((c)[1]), "+f"((c)[2]), "+f"((c)[3]) \
        : "r"((a)[0]),"r"((a)[1]),"r"((a)[2]),"r"((a)[3]), "r"(b0), "r"(b1))

/* fp32 -> fp16 conversion: x */
__global__ __launch_bounds__(256) void cvt_kernel(
    const float* __restrict__ in, uint32_t* __restrict__ oh, int n2)
{
    int i = blockIdx.x * 256 + threadIdx.x;
    if (i < n2) {
        float2 v = reinterpret_cast<const float2*>(in)[i];
        oh[i] = pack_h2(v.x, v.y);
    }
}

/* fp32 -> fp16 conversion of all 5 weights in one launch (blockIdx.y selects) */
__global__ __launch_bounds__(256) void cvt_w5_kernel(
    const float* __restrict__ s0, const float* __restrict__ s1,
    const float* __restrict__ s2, const float* __restrict__ s3,
    const float* __restrict__ s4,
    uint32_t* __restrict__ wqkv, uint32_t* __restrict__ w1,
    uint32_t* __restrict__ w2, int n2)
{
    int i = blockIdx.x * 256 + threadIdx.x;
    if (i >= n2) return;
    const int y = blockIdx.y;
    const float* s = (y == 0) ? s0 : (y == 1) ? s1 : (y == 2) ? s2 : (y == 3) ? s3 : s4;
    uint32_t* d = (y < 3) ? (wqkv + (size_t)y * n2) : (y == 3) ? w1 : w2;
    float2 v = reinterpret_cast<const float2*>(s)[i];
    d[i] = pack_h2(v.x, v.y);
}

/* ---------------------------------------------------------------------------
 * fp16 GEMM, mma.sync m16n8k16, fp32 accumulate.
 * CTA tile 128x128xBK32, 4 warps (2m x 2n), warp tile 64x64.
 * 4-stage cp.async pipeline, one __syncthreads per stage, 2 CTAs/SM.
 * nn=0: C = A[M,K] * B[N,K]^T ; nn=1: C = A[M,K] * B[K,N] (ldbn row stride).
 * qkv=1: N spans 3 segments of HID; route per-CTA to C/C2/C3 with per-seg bias,
 *        ReLU on segments 0,1 only.
 * ------------------------------------------------------------------------ */
__global__ __launch_bounds__(NTHREADS, 2) void gemm_fp16(
    const fp16* __restrict__ A, const fp16* __restrict__ B,
    int K, int nn, int ldbn,
    size_t sA, size_t sB, size_t sC,
    float* __restrict__ Cf, fp16* __restrict__ Ch,
    fp16* __restrict__ Ch2, fp16* __restrict__ Ch3,
    int ldc,
    const float* __restrict__ bias, const float* __restrict__ bias2,
    const float* __restrict__ bias3,
    const fp16* __restrict__ resh,
    const int* __restrict__ mask, int relu, int qkv)
{
    extern __shared__ char smraw[];
    const uint32_t sb = smem_u32(smraw);
    const int tid = threadIdx.x, lane = tid & 31, wid = tid >> 5;
    const int wm = wid & 1, wn = wid >> 1;            /* 2 x 2 warp grid */
    const int z = blockIdx.z, bm = blockIdx.y * BM, bn = blockIdx.x * BN;

    const fp16* Ag = A + z * sA + (size_t)bm * K;
    const fp16* Bg;
    if (nn) Bg = B + z * sB + bn;
    else    Bg = B + z * sB + (size_t)bn * K;

    float acc[4][8][4];
    #pragma unroll
    for (int i = 0; i < 4; i++)
        #pragma unroll
        for (int j = 0; j < 8; j++)
            #pragma unroll
            for (int t = 0; t < 4; t++) acc[i][j][t] = 0.f;

    auto issue = [&](int s) {
        const uint32_t stb = sb + (uint32_t)(s % NSTAGES) * STAGE_BYTES;
        const int k0 = s * BK;
        #pragma unroll
        for (int i = 0; i < 4; i++) {
            const int idx = tid + (i << 7);
            const int row = idx >> 2, c8 = (idx & 3) << 3;
            CP16(stb + row * 80 + (c8 << 1), Ag + (size_t)row * K + k0 + c8);
        }
        if (!nn) {
            #pragma unroll
            for (int i = 0; i < 4; i++) {
                const int idx = tid + (i << 7);
                const int row = idx >> 2, c8 = (idx & 3) << 3;
                CP16(stb + STG + row * 80 + (c8 << 1), Bg + (size_t)row * K + k0 + c8);
            }
        } else {
            #pragma unroll
            for (int i = 0; i < 4; i++) {
                const int idx = tid + (i << 7);
                const int row = idx >> 4, c8 = (idx & 15) << 3;
                CP16(stb + STG + row * 272 + (c8 << 1), Bg + (size_t)(k0 + row) * ldbn + c8);
            }
        }
    };

    auto compute = [&](int s) {
        const uint32_t stb = sb + (uint32_t)(s % NSTAGES) * STAGE_BYTES;
        #pragma unroll
        for (int ks = 0; ks < 2; ks++) {
            uint32_t ah[4][4];
            #pragma unroll
            for (int i = 0; i < 4; i++) {
                const int arow = wm * 64 + i * 16 + (lane & 15);
                LDSM4(ah[i], stb + arow * 80 + ((ks * 16 + ((lane >> 4) << 3)) << 1));
            }
            #pragma unroll
            for (int p = 0; p < 4; p++) {
                uint32_t bh[4];
                if (!nn) {
                    const int brow = wn * 64 + p * 16 + (lane & 7) + ((lane >> 4) << 3);
                    LDSM4(bh, stb + STG + brow * 80 +
                              ((ks * 16 + (((lane >> 3) & 1) << 3)) << 1));
                } else {
                    const int krow = ks * 16 + (lane & 7) + (((lane >> 3) & 1) << 3);
                    const int ncol = wn * 64 + p * 16 + ((lane >> 4) << 3);
                    LDSM4T(bh, stb + STG + krow * 272 + (ncol << 1));
                }
                #pragma unroll
                for (int i = 0; i < 4; i++)
                    #pragma unroll
                    for (int jj = 0; jj < 2; jj++)
                        MMA(acc[i][p * 2 + jj], ah[i], bh[jj * 2], bh[jj * 2 + 1]);
            }
        }
    };

    const int NSt = K / BK;
    issue(0); CPCOMMIT();
    issue(1); CPCOMMIT();
    issue(2); CPCOMMIT();
    for (int s = 0; s < NSt; s++) {
        CPWAIT2();
        __syncthreads();
        if (s + 3 < NSt) issue(s + 3);
        CPCOMMIT();
        compute(s);
    }

    /* ---- epilogue ---- */
    if (mask) {
        const int* mk = mask + (size_t)z * SEQ;
        float* Cfz = Cf + z * sC;
        #pragma unroll
        for (int i = 0; i < 4; i++) {
            const int r0 = bm + wm * 64 + i * 16 + (lane >> 2);
            const float m0 = (float)mk[r0], m1 = (float)mk[r0 + 8];
            #pragma unroll
            for (int j = 0; j < 8; j++) {
                const int c = bn + wn * 64 + j * 8 + ((lane & 3) << 1);
                const float mc0 = (float)mk[c], mc1 = (float)mk[c + 1];
                float ax = acc[i][j][0] * SCALE_QK - (1.f - m0 * mc0) * 1e12f;
                float ay = acc[i][j][1] * SCALE_QK - (1.f - m0 * mc1) * 1e12f;
                float az = acc[i][j][2] * SCALE_QK - (1.f - m1 * mc0) * 1e12f;
                float aw = acc[i][j][3] * SCALE_QK - (1.f - m1 * mc1) * 1e12f;
                const size_t o0 = (size_t)r0 * ldc + c, o1 = o0 + (size_t)8 * ldc;
                *(float2*)&Cfz[o0] = make_float2(ax, ay);
                *(float2*)&Cfz[o1] = make_float2(az, aw);
            }
        }
    } else if (qkv) {
        const int seg = bn / HID;
        fp16* dst = (seg == 0) ? Ch : (seg == 1) ? Ch2 : Ch3;
        const float* bs = (seg == 0) ? bias : (seg == 1) ? bias2 : bias3;
        const int cb = bn - seg * HID;
        const int dorelu = (seg < 2);
        #pragma unroll
        for (int i = 0; i < 4; i++) {
            const int r0 = bm + wm * 64 + i * 16 + (lane >> 2);
            #pragma unroll
            for (int j = 0; j < 8; j++) {
                const int cl = cb + wn * 64 + j * 8 + ((lane & 3) << 1);
                const float b0 = bs[cl], b1 = bs[cl + 1];
                float ax = acc[i][j][0] + b0, ay = acc[i][j][1] + b1;
                float az = acc[i][j][2] + b0, aw = acc[i][j][3] + b1;
                if (dorelu) {
                    ax = fmaxf(ax, 0.f); ay = fmaxf(ay, 0.f);
                    az = fmaxf(az, 0.f); aw = fmaxf(aw, 0.f);
                }
                const size_t o0 = (size_t)r0 * HID + cl, o1 = o0 + (size_t)8 * HID;
                *(uint32_t*)((char*)dst + o0 * 2) = pack_h2(ax, ay);
                *(uint32_t*)((char*)dst + o1 * 2) = pack_h2(az, aw);
            }
        }
    } else {
        float* Cfz = Cf ? (Cf + z * sC) : (float*)0;
        fp16*  Chz = Ch ? (Ch + z * sC) : (fp16*)0;
        #pragma unroll
        for (int i = 0; i < 4; i++) {
            const int r0 = bm + wm * 64 + i * 16 + (lane >> 2);
            #pragma unroll
            for (int j = 0; j < 8; j++) {
                const int c = bn + wn * 64 + j * 8 + ((lane & 3) << 1);
                float ax = acc[i][j][0], ay = acc[i][j][1];
                float az = acc[i][j][2], aw = acc[i][j][3];
                if (bias) {
                    const float b0 = bias[c], b1 = bias[c + 1];
                    ax += b0; ay += b1; az += b0; aw += b1;
                }
                if (relu) {
                    ax = fmaxf(ax, 0.f); ay = fmaxf(ay, 0.f);
                    az = fmaxf(az, 0.f); aw = fmaxf(aw, 0.f);
                }
                const size_t o0 = (size_t)r0 * ldc + c, o1 = o0 + (size_t)8 * ldc;
                if (resh) {
                    const __half2 q0 = *(const __half2*)((const char*)resh + o0 * 2);
                    const __half2 q1 = *(const __half2*)((const char*)resh + o1 * 2);
                    const float2 f0 = __half22float2(q0), f1 = __half22float2(q1);
                    ax += f0.x; ay += f0.y; az += f1.x; aw += f1.y;
                }
                if (Cfz) {
                    *(float2*)&Cfz[o0] = make_float2(ax, ay);
                    *(float2*)&Cfz[o1] = make_float2(az, aw);
                }
                if (Chz) {
                    *(uint32_t*)((char*)Chz + o0 * 2) = pack_h2(ax, ay);
                    *(uint32_t*)((char*)Chz + o1 * 2) = pack_h2(az, aw);
                }
            }
        }
    }
}

/* ---- row softmax, fp32 in -> fp16 out, fused mask ---- */
__global__ __launch_bounds__(256) void softmax_kernel(
    const float* __restrict__ Sc, fp16* __restrict__ Wout,
    const int* __restrict__ mask)
{
    const int b = blockIdx.y, row = blockIdx.x, tid = threadIdx.x;
    const float* srow = Sc + ((size_t)b * SEQ + row) * SEQ;
    const int* mrow = mask + (size_t)b * SEQ;
    float4 x = *(const float4*)(srow + tid * 4);

    float mx = fmaxf(fmaxf(x.x, x.y), fmaxf(x.z, x.w));
    #pragma unroll
    for (int o = 16; o > 0; o >>= 1) mx = fmaxf(mx, __shfl_xor_sync(~0u, mx, o));
    __shared__ float red[8];
    if ((tid & 31) == 0) red[tid >> 5] = mx;
    __syncthreads();
    float rmx = red[0];
    #pragma unroll
    for (int i = 1; i < 8; i++) rmx = fmaxf(rmx, red[i]);

    float e0 = expf(x.x - rmx), e1 = expf(x.y - rmx);
    float e2 = expf(x.z - rmx), e3 = expf(x.w - rmx);
    float s = e0 + e1 + e2 + e3;
    #pragma unroll
    for (int o = 16; o > 0; o >>= 1) s += __shfl_xor_sync(~0u, s, o);
    __syncthreads();
    if ((tid & 31) == 0) red[tid >> 5] = s;
    __syncthreads();
    float tot = red[0];
    #pragma unroll
    for (int i = 1; i < 8; i++) tot += red[i];

    const float cns = (1.0f / tot) * (float)mrow[row];
    const float o0 = e0 * cns * (float)mrow[tid * 4 + 0];
    const float o1 = e1 * cns * (float)mrow[tid * 4 + 1];
    const float o2 = e2 * cns * (float)mrow[tid * 4 + 2];
    const float o3 = e3 * cns * (float)mrow[tid * 4 + 3];

    const size_t off = (((size_t)b * SEQ + row) * SEQ + tid * 4) * 2;
    *(uint2*)((char*)Wout + off) = make_uint2(pack_h2(o0, o1), pack_h2(o2, o3));
}

/* --------------------------------------------------------------------- */
extern "C" void kernel_launch(void* const* d_in, const int* in_sizes, int n_in,
                              void* d_out, int out_size)
{
    const float* x    = (const float*)d_in[0];
    const int*   mask = (const int*)  d_in[1];
    const float* Wq = (const float*)d_in[2];
    const float* bq = (const float*)d_in[3];
    const float* Wk = (const float*)d_in[4];
    const float* bk = (const float*)d_in[5];
    const float* Wv = (const float*)d_in[6];
    const float* bv = (const float*)d_in[7];
    const float* W1 = (const float*)d_in[8];
    const float* b1 = (const float*)d_in[9];
    const float* W2 = (const float*)d_in[10];
    const float* b2 = (const float*)d_in[11];
    float* out = (float*)d_out;

    fp16 *xh,*qh,*kh,*vh,*oh,*h1h,*wqkv,*w1h,*w2h,*wh;
    float *sc;
    cudaGetSymbolAddress((void**)&xh,   g_x);
    cudaGetSymbolAddress((void**)&qh,   g_q);
    cudaGetSymbolAddress((void**)&kh,   g_k);
    cudaGetSymbolAddress((void**)&vh,   g_v);
    cudaGetSymbolAddress((void**)&oh,   g_o);
    cudaGetSymbolAddress((void**)&h1h,  g_h1);
    cudaGetSymbolAddress((void**)&wqkv, g_wqkv);
    cudaGetSymbolAddress((void**)&w1h,  g_w1);
    cudaGetSymbolAddress((void**)&w2h,  g_w2);
    cudaGetSymbolAddress((void**)&wh,   g_w);
    cudaGetSymbolAddress((void**)&sc,   g_sc);

    cudaFuncSetAttribute(gemm_fp16, cudaFuncAttributeMaxDynamicSharedMemorySize, SMEM_GEMM);

    dim3 blk(NTHREADS);
    const size_t sBH = (size_t)SEQ * HID, sBS = (size_t)SEQ * SEQ;
    dim3 gqkv(3 * HID / BN, (NB * SEQ) / BM, 1);  /* (18, 128) */
    dim3 gproj(HID / BN, (NB * SEQ) / BM, 1);     /* (6, 128) */
    dim3 gsc(SEQ / BN, SEQ / BM, NB);             /* (8, 8, 16) */
    dim3 gpv(HID / BN, SEQ / BM, NB);             /* (6, 8, 16) */

    cvt_kernel<<<(NXE/2 + 255)/256, 256>>>(x, (uint32_t*)xh, NXE/2);
    cvt_w5_kernel<<<dim3((NWE/2 + 255)/256, 5), 256>>>(
        Wq, Wk, Wv, W1, W2,
        (uint32_t*)wqkv, (uint32_t*)w1h, (uint32_t*)w2h, NWE/2);

    /* fused q,k,v projection */
    gemm_fp16<<<gqkv, blk, SMEM_GEMM>>>(xh, wqkv, HID, 0, 0, 0, 0, 0,
        nullptr, qh, kh, vh, HID, bq, bk, bv, nullptr, nullptr, 0, 1);

    /* scores = q k^T * scale - mask penalty (fp32 out) */
    gemm_fp16<<<gsc, blk, SMEM_GEMM>>>(qh, kh, HID, 0, 0, sBH, sBH, sBS,
        sc, nullptr, nullptr, nullptr, SEQ, nullptr, nullptr, nullptr,
        nullptr, mask, 0, 0);

    softmax_kernel<<<dim3(SEQ, NB), 256>>>(sc, wh, mask);

    /* O = W V  (NN), fp16 out only */
    gemm_fp16<<<gpv, blk, SMEM_GEMM>>>(wh, vh, SEQ, 1, HID, sBS, sBH, sBH,
        nullptr, oh, nullptr, nullptr, HID, nullptr, nullptr, nullptr,
        nullptr, nullptr, 0, 0);

    /* FFN */
    gemm_fp16<<<gproj, blk, SMEM_GEMM>>>(oh, w1h, HID, 0, 0, 0, 0, 0,
        nullptr, h1h, nullptr, nullptr, HID, b1, nullptr, nullptr,
        nullptr, nullptr, 1, 0);
    gemm_fp16<<<gproj, blk, SMEM_GEMM>>>(h1h, w2h, HID, 0, 0, 0, 0, 0,
        out, nullptr, nullptr, nullptr, HID, b2, nullptr, nullptr,
        oh, nullptr, 0, 0);
}